// round 3
// baseline (speedup 1.0000x reference)
#include <cuda_runtime.h>
#include <cuda_bf16.h>
#include <cstdint>

// Problem dims
#define NB   16384
#define NF   1024
#define NH   64
#define ND   256
#define NTE  4
#define NCE  4
#define BD   (NB * ND)       // 4194304

// ---------------------------------------------------------------------------
// Scratch (device globals — no allocations allowed)
// ---------------------------------------------------------------------------
__device__ float g_hid[3ull * NB * 256];   // per-group hidden [B, 4*64], relu'd
__device__ float g_gates[(size_t)NB * 28]; // per row: gA[8] | gS[12] | gB[8]

// ---------------------------------------------------------------------------
// Packed f32x2 helpers (sm_100+ PTX)
// ---------------------------------------------------------------------------
#define FMA2(acc, a, b) \
    asm("fma.rn.f32x2 %0, %1, %2, %0;" : "+l"(acc) : "l"(a), "l"(b))
#define PACK2(dst, lo, hi) \
    asm("mov.b64 %0, {%1, %2};" : "=l"(dst) : "r"(lo), "r"(hi))
#define UNPACK2(lo, hi, v) \
    asm("mov.b64 {%0, %1}, %2;" : "=r"(lo), "=r"(hi) : "l"(v))

// ---------------------------------------------------------------------------
// Kernel 1: layer-1 GEMM for all 3 groups.
//   C[b, e*64+h] = relu( sum_f x[b,f] * W1[e,f,h] + b1[e,h] )
// Tile 128x128, K-step 8, 256 threads, 8x8 microtile via f32x2 (8 rows x 4 col-pairs).
// ---------------------------------------------------------------------------
struct G1Args {
    const float* x[3];
    const float* W1[3];
    const float* b1[3];
};

__global__ __launch_bounds__(256) void gemm1_kernel(G1Args args) {
    const int grp = blockIdx.z;
    const float* __restrict__ x  = args.x[grp];
    const float* __restrict__ W1 = args.W1[grp];
    const float* __restrict__ b1 = args.b1[grp];

    __shared__ float Xs[8][128];   // [k][row]
    __shared__ float Ws[8][128];   // [k][col]

    const int t    = threadIdx.x;
    const int row0 = blockIdx.y * 128;
    const int n0   = blockIdx.x * 128;   // 0 or 128

    // global-load assignments
    const int xr = t >> 1;            // 0..127 (row within tile)
    const int xk = (t & 1) * 4;       // 0 or 4 (k offset)
    const int wk = t >> 5;            // 0..7   (k)
    const int wc = (t & 31) * 4;      // 0..124 (col within tile)
    const int we = (n0 + wc) >> 6;    // expert of this col
    const int wh = (n0 + wc) & 63;    // h within expert

    const float4* xg = (const float4*)(x + (size_t)(row0 + xr) * NF + xk);
    const float4* wg = (const float4*)(W1 + (size_t)we * NF * NH + (size_t)wk * NH + wh);

    const int tyr = (t >> 4) * 8;     // row base of microtile
    const int txc = (t & 15) * 8;     // col base of microtile

    unsigned long long acc[8][4];
    #pragma unroll
    for (int i = 0; i < 8; i++)
        #pragma unroll
        for (int j = 0; j < 4; j++) acc[i][j] = 0ull;

    float4 xa = *xg;
    float4 wa = *wg;

    for (int ks = 0; ks < NF / 8; ks++) {
        __syncthreads();
        Xs[xk + 0][xr] = xa.x;
        Xs[xk + 1][xr] = xa.y;
        Xs[xk + 2][xr] = xa.z;
        Xs[xk + 3][xr] = xa.w;
        *(float4*)&Ws[wk][wc] = wa;
        __syncthreads();
        if (ks < NF / 8 - 1) {
            xg += 2;          // +8 floats along f
            wg += (8 * NH) / 4; // +8 rows of W (f dim)
            xa = *xg;
            wa = *wg;
        }
        #pragma unroll
        for (int kk = 0; kk < 8; kk++) {
            float a[8];
            *(float4*)&a[0] = *(const float4*)&Xs[kk][tyr];
            *(float4*)&a[4] = *(const float4*)&Xs[kk][tyr + 4];
            unsigned long long bp[4];
            #pragma unroll
            for (int j = 0; j < 4; j++)
                bp[j] = *(const unsigned long long*)&Ws[kk][txc + 2 * j];
            #pragma unroll
            for (int i = 0; i < 8; i++) {
                unsigned long long ap;
                unsigned int au = __float_as_uint(a[i]);
                PACK2(ap, au, au);
                #pragma unroll
                for (int j = 0; j < 4; j++) FMA2(acc[i][j], ap, bp[j]);
            }
        }
    }

    // epilogue: bias + relu, store pairs
    float* hb = g_hid + (size_t)grp * NB * 256;
    #pragma unroll
    for (int i = 0; i < 8; i++) {
        const int row = row0 + tyr + i;
        float* orow = hb + (size_t)row * 256 + n0 + txc;
        #pragma unroll
        for (int j = 0; j < 4; j++) {
            unsigned int u0, u1;
            UNPACK2(u0, u1, acc[i][j]);
            const int gc = n0 + txc + 2 * j;
            const int ee = gc >> 6;
            const int hh = gc & 63;
            float v0 = __uint_as_float(u0) + b1[ee * 64 + hh];
            float v1 = __uint_as_float(u1) + b1[ee * 64 + hh + 1];
            float2 st;
            st.x = fmaxf(v0, 0.f);
            st.y = fmaxf(v1, 0.f);
            *(float2*)(orow + 2 * j) = st;
        }
    }
}

// ---------------------------------------------------------------------------
// Kernel 2: gates. One warp per row. G in {8,12}. Writes softmax(x@Wg+bg).
// ---------------------------------------------------------------------------
template <int G>
__global__ __launch_bounds__(256) void gate_kernel(const float* __restrict__ x,
                                                   const float* __restrict__ Wg,
                                                   const float* __restrict__ bg,
                                                   int off) {
    __shared__ float sm[8][12];
    const int w    = threadIdx.x >> 5;
    const int lane = threadIdx.x & 31;
    const size_t b = (size_t)blockIdx.x * 8 + w;

    const float* xr = x + b * NF;
    float acc[G];
    #pragma unroll
    for (int c = 0; c < G; c++) acc[c] = 0.f;

    for (int f = lane; f < NF; f += 32) {
        const float xv = xr[f];
        const float* wr = Wg + (size_t)f * G;
        #pragma unroll
        for (int c = 0; c < G; c++) acc[c] += xv * wr[c];
    }
    #pragma unroll
    for (int c = 0; c < G; c++) {
        #pragma unroll
        for (int o = 16; o > 0; o >>= 1)
            acc[c] += __shfl_xor_sync(0xffffffffu, acc[c], o);
    }
    if (lane == 0) {
        #pragma unroll
        for (int c = 0; c < G; c++) sm[w][c] = acc[c];
    }
    __syncwarp();

    float logit = -1e30f;
    if (lane < G) logit = sm[w][lane] + bg[lane];
    float m = logit;
    #pragma unroll
    for (int o = 16; o > 0; o >>= 1)
        m = fmaxf(m, __shfl_xor_sync(0xffffffffu, m, o));
    float ex = (lane < G) ? expf(logit - m) : 0.f;
    float s = ex;
    #pragma unroll
    for (int o = 16; o > 0; o >>= 1)
        s += __shfl_xor_sync(0xffffffffu, s, o);
    if (lane < G) g_gates[b * 28 + off + lane] = ex / s;
}

// ---------------------------------------------------------------------------
// Kernel 3: layer-2 (per-expert [16,64]x[64,256]) + relu + gated combine.
// Block: 256 threads = 256 output cols, 16 rows per block. Loops 12 experts,
// staging each W2[e] (64KB) in dynamic smem. FFMA2 pairs over even/odd h.
// ---------------------------------------------------------------------------
struct CArgs {
    const float* W2[3];
    const float* b2[3];
};

#define CS_W2  0
#define CS_HS  16384
#define CS_B2  (16384 + 1024)
#define CS_GS  (16384 + 1024 + 256)
#define CS_FLOATS (16384 + 1024 + 256 + 16 * 28)
#define CS_BYTES (CS_FLOATS * 4)

extern __shared__ float cs[];

__global__ __launch_bounds__(256) void combine_kernel(CArgs args, float* __restrict__ out) {
    float* W2s = cs + CS_W2;   // [64][256]
    float* Hs  = cs + CS_HS;   // [16][64]
    float* b2s = cs + CS_B2;   // [256]
    float* gsh = cs + CS_GS;   // [16][28]

    const int t    = threadIdx.x;         // output column
    const int row0 = blockIdx.x * 16;

    for (int i = t; i < 16 * 28; i += 256)
        gsh[i] = g_gates[(size_t)(row0 + i / 28) * 28 + (i % 28)];

    float oA[16], oS[16], oB[16];
    #pragma unroll
    for (int r = 0; r < 16; r++) { oA[r] = 0.f; oS[r] = 0.f; oB[r] = 0.f; }

    const int hr = t >> 4;            // 0..15 row for Hs load
    const int h4 = (t & 15) * 4;      // 0..60

    for (int e = 0; e < 12; e++) {
        const int grp = e >> 2;
        const int el  = e & 3;
        __syncthreads();
        // stage W2[grp][el] : [64,256]
        const float4* w2g = (const float4*)(args.W2[grp] + (size_t)el * NH * ND);
        float4* w2s4 = (float4*)W2s;
        #pragma unroll
        for (int i = 0; i < 16; i++) w2s4[i * 256 + t] = w2g[i * 256 + t];
        b2s[t] = args.b2[grp][el * 256 + t];
        // stage Hs : [16,64]
        *(float4*)&Hs[hr * 64 + h4] =
            *(const float4*)(g_hid + (size_t)grp * NB * 256 +
                             (size_t)(row0 + hr) * 256 + el * 64 + h4);
        __syncthreads();

        unsigned long long tp[16];
        #pragma unroll
        for (int r = 0; r < 16; r++) tp[r] = 0ull;

        #pragma unroll
        for (int hp = 0; hp < 32; hp++) {
            const float w0 = W2s[(2 * hp) * 256 + t];
            const float w1 = W2s[(2 * hp + 1) * 256 + t];
            unsigned long long wp;
            PACK2(wp, __float_as_uint(w0), __float_as_uint(w1));
            #pragma unroll
            for (int r = 0; r < 16; r++) {
                const unsigned long long hv =
                    *(const unsigned long long*)&Hs[r * 64 + 2 * hp];
                FMA2(tp[r], hv, wp);
            }
        }

        #pragma unroll
        for (int r = 0; r < 16; r++) {
            unsigned int u0, u1;
            UNPACK2(u0, u1, tp[r]);
            float val = __uint_as_float(u0) + __uint_as_float(u1) + b2s[t];
            val = fmaxf(val, 0.f);
            const float* g = &gsh[r * 28];
            const float cS = g[8 + e];
            float cA = 0.f, cB = 0.f;
            if (e < 8) cA = g[e];
            if (e >= 8) cB = g[12 + e];          // gB[e-8]
            else if (e >= 4) cB = g[20 + e];     // gB[4 + (e-4)]
            oA[r] += cA * val;
            oS[r] += cS * val;
            oB[r] += cB * val;
        }
    }

    #pragma unroll
    for (int r = 0; r < 16; r++) {
        const size_t rowoff = (size_t)(row0 + r) * 256 + t;
        out[rowoff]            = oA[r];
        out[(size_t)BD + rowoff]   = oS[r];
        out[2ull * BD + rowoff]    = oB[r];
    }
}

// ---------------------------------------------------------------------------
// Launcher
// ---------------------------------------------------------------------------
extern "C" void kernel_launch(void* const* d_in, const int* in_sizes, int n_in,
                              void* d_out, int out_size) {
    (void)in_sizes; (void)n_in; (void)out_size;
    const float* x_A = (const float*)d_in[0];
    const float* x_S = (const float*)d_in[1];
    const float* x_B = (const float*)d_in[2];
    const float* W1A = (const float*)d_in[3];
    const float* b1A = (const float*)d_in[4];
    const float* W2A = (const float*)d_in[5];
    const float* b2A = (const float*)d_in[6];
    const float* W1S = (const float*)d_in[7];
    const float* b1S = (const float*)d_in[8];
    const float* W2S = (const float*)d_in[9];
    const float* b2S = (const float*)d_in[10];
    const float* W1B = (const float*)d_in[11];
    const float* b1B = (const float*)d_in[12];
    const float* W2B = (const float*)d_in[13];
    const float* b2B = (const float*)d_in[14];
    const float* WgA = (const float*)d_in[15];
    const float* bgA = (const float*)d_in[16];
    const float* WgB = (const float*)d_in[17];
    const float* bgB = (const float*)d_in[18];
    const float* WgS = (const float*)d_in[19];
    const float* bgS = (const float*)d_in[20];
    float* out = (float*)d_out;

    G1Args g1;
    g1.x[0] = x_A;  g1.x[1] = x_S;  g1.x[2] = x_B;
    g1.W1[0] = W1A; g1.W1[1] = W1S; g1.W1[2] = W1B;
    g1.b1[0] = b1A; g1.b1[1] = b1S; g1.b1[2] = b1B;
    gemm1_kernel<<<dim3(2, NB / 128, 3), 256>>>(g1);

    gate_kernel<8><<<NB / 8, 256>>>(x_A, WgA, bgA, 0);
    gate_kernel<12><<<NB / 8, 256>>>(x_S, WgS, bgS, 8);
    gate_kernel<8><<<NB / 8, 256>>>(x_B, WgB, bgB, 20);

    CArgs c2;
    c2.W2[0] = W2A; c2.W2[1] = W2S; c2.W2[2] = W2B;
    c2.b2[0] = b2A; c2.b2[1] = b2S; c2.b2[2] = b2B;
    cudaFuncSetAttribute(combine_kernel,
                         cudaFuncAttributeMaxDynamicSharedMemorySize, CS_BYTES);
    combine_kernel<<<NB / 16, 256, CS_BYTES>>>(c2, out);
}

// round 4
// speedup vs baseline: 1.0009x; 1.0009x over previous
#include <cuda_runtime.h>
#include <cuda_bf16.h>
#include <cstdint>

// Problem dims
#define NB   16384
#define NF   1024
#define NH   64
#define ND   256
#define NTE  4
#define NCE  4
#define BD   (NB * ND)       // 4194304

// ---------------------------------------------------------------------------
// Scratch (device globals — no allocations allowed)
// ---------------------------------------------------------------------------
__device__ float g_hid[3ull * NB * 256];   // per-group hidden [B, 4*64], relu'd
__device__ float g_gates[(size_t)NB * 28]; // per row: gA[8] | gS[12] | gB[8]

// ---------------------------------------------------------------------------
// Packed f32x2 helpers (sm_100+ PTX)
// ---------------------------------------------------------------------------
#define FMA2(acc, a, b) \
    asm("fma.rn.f32x2 %0, %1, %2, %0;" : "+l"(acc) : "l"(a), "l"(b))
#define PACK2(dst, lo, hi) \
    asm("mov.b64 %0, {%1, %2};" : "=l"(dst) : "r"(lo), "r"(hi))
#define UNPACK2(lo, hi, v) \
    asm("mov.b64 {%0, %1}, %2;" : "=r"(lo), "=r"(hi) : "l"(v))

// ---------------------------------------------------------------------------
// Kernel 1: layer-1 GEMM for all 3 groups.
//   C[b, e*64+h] = relu( sum_f x[b,f] * W1[e,f,h] + b1[e,h] )
// Tile 128x128, K-step 8, 256 threads, 8x8 microtile via f32x2 (8 rows x 4 col-pairs).
// ---------------------------------------------------------------------------
struct G1Args {
    const float* x[3];
    const float* W1[3];
    const float* b1[3];
};

__global__ __launch_bounds__(256) void gemm1_kernel(G1Args args) {
    const int grp = blockIdx.z;
    const float* __restrict__ x  = args.x[grp];
    const float* __restrict__ W1 = args.W1[grp];
    const float* __restrict__ b1 = args.b1[grp];

    __shared__ float Xs[8][128];   // [k][row]
    __shared__ float Ws[8][128];   // [k][col]

    const int t    = threadIdx.x;
    const int row0 = blockIdx.y * 128;
    const int n0   = blockIdx.x * 128;   // 0 or 128

    // global-load assignments
    const int xr = t >> 1;            // 0..127 (row within tile)
    const int xk = (t & 1) * 4;       // 0 or 4 (k offset)
    const int wk = t >> 5;            // 0..7   (k)
    const int wc = (t & 31) * 4;      // 0..124 (col within tile)
    const int we = (n0 + wc) >> 6;    // expert of this col
    const int wh = (n0 + wc) & 63;    // h within expert

    const float4* xg = (const float4*)(x + (size_t)(row0 + xr) * NF + xk);
    const float4* wg = (const float4*)(W1 + (size_t)we * NF * NH + (size_t)wk * NH + wh);

    const int tyr = (t >> 4) * 8;     // row base of microtile
    const int txc = (t & 15) * 8;     // col base of microtile

    unsigned long long acc[8][4];
    #pragma unroll
    for (int i = 0; i < 8; i++)
        #pragma unroll
        for (int j = 0; j < 4; j++) acc[i][j] = 0ull;

    float4 xa = *xg;
    float4 wa = *wg;

    for (int ks = 0; ks < NF / 8; ks++) {
        __syncthreads();
        Xs[xk + 0][xr] = xa.x;
        Xs[xk + 1][xr] = xa.y;
        Xs[xk + 2][xr] = xa.z;
        Xs[xk + 3][xr] = xa.w;
        *(float4*)&Ws[wk][wc] = wa;
        __syncthreads();
        if (ks < NF / 8 - 1) {
            xg += 2;          // +8 floats along f
            wg += (8 * NH) / 4; // +8 rows of W (f dim)
            xa = *xg;
            wa = *wg;
        }
        #pragma unroll
        for (int kk = 0; kk < 8; kk++) {
            float a[8];
            *(float4*)&a[0] = *(const float4*)&Xs[kk][tyr];
            *(float4*)&a[4] = *(const float4*)&Xs[kk][tyr + 4];
            unsigned long long bp[4];
            #pragma unroll
            for (int j = 0; j < 4; j++)
                bp[j] = *(const unsigned long long*)&Ws[kk][txc + 2 * j];
            #pragma unroll
            for (int i = 0; i < 8; i++) {
                unsigned long long ap;
                unsigned int au = __float_as_uint(a[i]);
                PACK2(ap, au, au);
                #pragma unroll
                for (int j = 0; j < 4; j++) FMA2(acc[i][j], ap, bp[j]);
            }
        }
    }

    // epilogue: bias + relu, store pairs
    float* hb = g_hid + (size_t)grp * NB * 256;
    #pragma unroll
    for (int i = 0; i < 8; i++) {
        const int row = row0 + tyr + i;
        float* orow = hb + (size_t)row * 256 + n0 + txc;
        #pragma unroll
        for (int j = 0; j < 4; j++) {
            unsigned int u0, u1;
            UNPACK2(u0, u1, acc[i][j]);
            const int gc = n0 + txc + 2 * j;
            const int ee = gc >> 6;
            const int hh = gc & 63;
            float v0 = __uint_as_float(u0) + b1[ee * 64 + hh];
            float v1 = __uint_as_float(u1) + b1[ee * 64 + hh + 1];
            float2 st;
            st.x = fmaxf(v0, 0.f);
            st.y = fmaxf(v1, 0.f);
            *(float2*)(orow + 2 * j) = st;
        }
    }
}

// ---------------------------------------------------------------------------
// Kernel 2: gates. One warp per row. G in {8,12}. Writes softmax(x@Wg+bg).
// ---------------------------------------------------------------------------
template <int G>
__global__ __launch_bounds__(256) void gate_kernel(const float* __restrict__ x,
                                                   const float* __restrict__ Wg,
                                                   const float* __restrict__ bg,
                                                   int off) {
    __shared__ float sm[8][12];
    const int w    = threadIdx.x >> 5;
    const int lane = threadIdx.x & 31;
    const size_t b = (size_t)blockIdx.x * 8 + w;

    const float* xr = x + b * NF;
    float acc[G];
    #pragma unroll
    for (int c = 0; c < G; c++) acc[c] = 0.f;

    for (int f = lane; f < NF; f += 32) {
        const float xv = xr[f];
        const float* wr = Wg + (size_t)f * G;
        #pragma unroll
        for (int c = 0; c < G; c++) acc[c] += xv * wr[c];
    }
    #pragma unroll
    for (int c = 0; c < G; c++) {
        #pragma unroll
        for (int o = 16; o > 0; o >>= 1)
            acc[c] += __shfl_xor_sync(0xffffffffu, acc[c], o);
    }
    if (lane == 0) {
        #pragma unroll
        for (int c = 0; c < G; c++) sm[w][c] = acc[c];
    }
    __syncwarp();

    float logit = -1e30f;
    if (lane < G) logit = sm[w][lane] + bg[lane];
    float m = logit;
    #pragma unroll
    for (int o = 16; o > 0; o >>= 1)
        m = fmaxf(m, __shfl_xor_sync(0xffffffffu, m, o));
    float ex = (lane < G) ? expf(logit - m) : 0.f;
    float s = ex;
    #pragma unroll
    for (int o = 16; o > 0; o >>= 1)
        s += __shfl_xor_sync(0xffffffffu, s, o);
    if (lane < G) g_gates[b * 28 + off + lane] = ex / s;
}

// ---------------------------------------------------------------------------
// Kernel 3: layer-2 (per-expert [16,64]x[64,256]) + relu + gated combine.
// Block: 256 threads = 256 output cols, 16 rows per block. Loops 12 experts,
// staging each W2[e] (64KB) in dynamic smem. FFMA2 pairs over even/odd h.
// ---------------------------------------------------------------------------
struct CArgs {
    const float* W2[3];
    const float* b2[3];
};

#define CS_W2  0
#define CS_HS  16384
#define CS_B2  (16384 + 1024)
#define CS_GS  (16384 + 1024 + 256)
#define CS_FLOATS (16384 + 1024 + 256 + 16 * 28)
#define CS_BYTES (CS_FLOATS * 4)

extern __shared__ float cs[];

__global__ __launch_bounds__(256) void combine_kernel(CArgs args, float* __restrict__ out) {
    float* W2s = cs + CS_W2;   // [64][256]
    float* Hs  = cs + CS_HS;   // [16][64]
    float* b2s = cs + CS_B2;   // [256]
    float* gsh = cs + CS_GS;   // [16][28]

    const int t    = threadIdx.x;         // output column
    const int row0 = blockIdx.x * 16;

    for (int i = t; i < 16 * 28; i += 256)
        gsh[i] = g_gates[(size_t)(row0 + i / 28) * 28 + (i % 28)];

    float oA[16], oS[16], oB[16];
    #pragma unroll
    for (int r = 0; r < 16; r++) { oA[r] = 0.f; oS[r] = 0.f; oB[r] = 0.f; }

    const int hr = t >> 4;            // 0..15 row for Hs load
    const int h4 = (t & 15) * 4;      // 0..60

    for (int e = 0; e < 12; e++) {
        const int grp = e >> 2;
        const int el  = e & 3;
        __syncthreads();
        // stage W2[grp][el] : [64,256]
        const float4* w2g = (const float4*)(args.W2[grp] + (size_t)el * NH * ND);
        float4* w2s4 = (float4*)W2s;
        #pragma unroll
        for (int i = 0; i < 16; i++) w2s4[i * 256 + t] = w2g[i * 256 + t];
        b2s[t] = args.b2[grp][el * 256 + t];
        // stage Hs : [16,64]
        *(float4*)&Hs[hr * 64 + h4] =
            *(const float4*)(g_hid + (size_t)grp * NB * 256 +
                             (size_t)(row0 + hr) * 256 + el * 64 + h4);
        __syncthreads();

        unsigned long long tp[16];
        #pragma unroll
        for (int r = 0; r < 16; r++) tp[r] = 0ull;

        #pragma unroll
        for (int hp = 0; hp < 32; hp++) {
            const float w0 = W2s[(2 * hp) * 256 + t];
            const float w1 = W2s[(2 * hp + 1) * 256 + t];
            unsigned long long wp;
            PACK2(wp, __float_as_uint(w0), __float_as_uint(w1));
            #pragma unroll
            for (int r = 0; r < 16; r++) {
                const unsigned long long hv =
                    *(const unsigned long long*)&Hs[r * 64 + 2 * hp];
                FMA2(tp[r], hv, wp);
            }
        }

        #pragma unroll
        for (int r = 0; r < 16; r++) {
            unsigned int u0, u1;
            UNPACK2(u0, u1, tp[r]);
            float val = __uint_as_float(u0) + __uint_as_float(u1) + b2s[t];
            val = fmaxf(val, 0.f);
            const float* g = &gsh[r * 28];
            const float cS = g[8 + e];
            float cA = 0.f, cB = 0.f;
            if (e < 8) cA = g[e];
            if (e >= 8) cB = g[12 + e];          // gB[e-8]
            else if (e >= 4) cB = g[20 + e];     // gB[4 + (e-4)]
            oA[r] += cA * val;
            oS[r] += cS * val;
            oB[r] += cB * val;
        }
    }

    #pragma unroll
    for (int r = 0; r < 16; r++) {
        const size_t rowoff = (size_t)(row0 + r) * 256 + t;
        out[rowoff]            = oA[r];
        out[(size_t)BD + rowoff]   = oS[r];
        out[2ull * BD + rowoff]    = oB[r];
    }
}

// ---------------------------------------------------------------------------
// Launcher
// ---------------------------------------------------------------------------
extern "C" void kernel_launch(void* const* d_in, const int* in_sizes, int n_in,
                              void* d_out, int out_size) {
    (void)in_sizes; (void)n_in; (void)out_size;
    const float* x_A = (const float*)d_in[0];
    const float* x_S = (const float*)d_in[1];
    const float* x_B = (const float*)d_in[2];
    const float* W1A = (const float*)d_in[3];
    const float* b1A = (const float*)d_in[4];
    const float* W2A = (const float*)d_in[5];
    const float* b2A = (const float*)d_in[6];
    const float* W1S = (const float*)d_in[7];
    const float* b1S = (const float*)d_in[8];
    const float* W2S = (const float*)d_in[9];
    const float* b2S = (const float*)d_in[10];
    const float* W1B = (const float*)d_in[11];
    const float* b1B = (const float*)d_in[12];
    const float* W2B = (const float*)d_in[13];
    const float* b2B = (const float*)d_in[14];
    const float* WgA = (const float*)d_in[15];
    const float* bgA = (const float*)d_in[16];
    const float* WgB = (const float*)d_in[17];
    const float* bgB = (const float*)d_in[18];
    const float* WgS = (const float*)d_in[19];
    const float* bgS = (const float*)d_in[20];
    float* out = (float*)d_out;

    G1Args g1;
    g1.x[0] = x_A;  g1.x[1] = x_S;  g1.x[2] = x_B;
    g1.W1[0] = W1A; g1.W1[1] = W1S; g1.W1[2] = W1B;
    g1.b1[0] = b1A; g1.b1[1] = b1S; g1.b1[2] = b1B;
    gemm1_kernel<<<dim3(2, NB / 128, 3), 256>>>(g1);

    gate_kernel<8><<<NB / 8, 256>>>(x_A, WgA, bgA, 0);
    gate_kernel<12><<<NB / 8, 256>>>(x_S, WgS, bgS, 8);
    gate_kernel<8><<<NB / 8, 256>>>(x_B, WgB, bgB, 20);

    CArgs c2;
    c2.W2[0] = W2A; c2.W2[1] = W2S; c2.W2[2] = W2B;
    c2.b2[0] = b2A; c2.b2[1] = b2S; c2.b2[2] = b2B;
    cudaFuncSetAttribute(combine_kernel,
                         cudaFuncAttributeMaxDynamicSharedMemorySize, CS_BYTES);
    combine_kernel<<<NB / 16, 256, CS_BYTES>>>(c2, out);
}

// round 9
// speedup vs baseline: 1.0420x; 1.0411x over previous
#include <cuda_runtime.h>
#include <cuda_bf16.h>
#include <cstdint>

// Problem dims
#define NB   16384
#define NF   1024
#define NH   64
#define ND   256
#define BD   (NB * ND)

// ---------------------------------------------------------------------------
// Scratch (device globals — no allocations allowed)
// ---------------------------------------------------------------------------
__device__ float g_hid[3ull * NB * 256];    // per-group hidden [B, 256], relu'd
__device__ float g_gates[(size_t)NB * 28];  // per row: gA[8] | gS[12] | gB[8]

extern __shared__ char dynsm[];

// ---------------------------------------------------------------------------
// Helpers
// ---------------------------------------------------------------------------
__device__ __forceinline__ float tf32r(float x) {      // round-to-nearest tf32
    uint32_t u;
    asm("cvt.rna.tf32.f32 %0, %1;" : "=r"(u) : "f"(x));
    return __uint_as_float(u);
}

// m16n8k8 tf32 MMA (plain sm_80+ PTX — works on non-'a' sm_103 target)
#define MMA_TF32(c, a, b) \
    asm("mma.sync.aligned.m16n8k8.row.col.f32.tf32.tf32.f32 " \
        "{%0,%1,%2,%3}, {%4,%5,%6,%7}, {%8,%9}, {%0,%1,%2,%3};" \
        : "+f"((c)[0]), "+f"((c)[1]), "+f"((c)[2]), "+f"((c)[3]) \
        : "r"((a)[0]), "r"((a)[1]), "r"((a)[2]), "r"((a)[3]), \
          "r"((b)[0]), "r"((b)[1]))

// Packed f32x2 helpers (combine kernel)
#define FMA2(acc, a, b) asm("fma.rn.f32x2 %0, %1, %2, %0;" : "+l"(acc) : "l"(a), "l"(b))
#define PACK2(dst, lo, hi) asm("mov.b64 %0, {%1, %2};" : "=l"(dst) : "r"(lo), "r"(hi))
#define UNPACK2(lo, hi, v) asm("mov.b64 {%0, %1}, %2;" : "=r"(lo), "=r"(hi) : "l"(v))

// ---------------------------------------------------------------------------
// Kernel 1: layer-1 via mma.sync tf32. CTA tile 128x128, K-chunk 16.
// 8 warps as 4(m) x 2(n); warp tile 32x64 = 2 m-atoms x 8 n-atoms.
//   C[b, e*64+h] = relu( sum_f x[b,f] * W1[e,f,h] + b1[e,h] )
// ---------------------------------------------------------------------------
struct G1Args { const float* x[3]; const float* W1[3]; const float* b1[3]; };

#define AST 20    // A smem row stride (floats): g*20+tt mod 32 -> 32 distinct banks
#define BST 136   // B smem row stride (floats): tt*8+g mod 32 -> 32 distinct banks

__global__ __launch_bounds__(256) void gemm1_kernel(G1Args args) {
    __shared__ float As[128 * AST];   // [m][k], k-chunk 16
    __shared__ float Bs[16 * BST];    // [k][n], n tile 128
    __shared__ float bias_s[256];

    const int t = threadIdx.x, lane = t & 31, w = t >> 5;
    const int wm = w >> 1, wn = w & 1;       // warp grid 4x2
    const int g = lane >> 2, tt = lane & 3;  // fragment coords
    const int row0 = blockIdx.x * 128;
    const int n0   = blockIdx.y * 128;
    const int grp  = blockIdx.z;
    const float* __restrict__ x  = args.x[grp];
    const float* __restrict__ W1 = args.W1[grp];

    bias_s[t] = args.b1[grp][t];

    // staging assignments
    const int arow = t >> 1;             // A row 0..127, 2 threads/row
    const int acb  = (t & 1) * 8;        // A k-offset 0 or 8
    const int bkr  = t >> 4;             // B k-row 0..15
    const int bnc  = (t & 15) * 8;       // B n-offset 0..120
    const int be   = (n0 + bnc) >> 6;    // expert of this col run
    const int bh   = (n0 + bnc) & 63;

    const float* xg  = x + (size_t)(row0 + arow) * NF + acb;
    const float* wgp = W1 + (size_t)be * NF * NH + (size_t)bkr * NH + bh;

    float acc[2][8][4];
    #pragma unroll
    for (int ma = 0; ma < 2; ma++)
        #pragma unroll
        for (int na = 0; na < 8; na++)
            #pragma unroll
            for (int i = 0; i < 4; i++) acc[ma][na][i] = 0.f;

    // prefetch chunk 0
    float4 a0v = *(const float4*)xg;
    float4 a1v = *(const float4*)(xg + 4);
    float4 b0v = *(const float4*)wgp;
    float4 b1v = *(const float4*)(wgp + 4);

    for (int c = 0; c < 64; c++) {
        __syncthreads();
        {
            float4 v;
            v = a0v; v.x = tf32r(v.x); v.y = tf32r(v.y); v.z = tf32r(v.z); v.w = tf32r(v.w);
            *(float4*)&As[arow * AST + acb] = v;
            v = a1v; v.x = tf32r(v.x); v.y = tf32r(v.y); v.z = tf32r(v.z); v.w = tf32r(v.w);
            *(float4*)&As[arow * AST + acb + 4] = v;
            v = b0v; v.x = tf32r(v.x); v.y = tf32r(v.y); v.z = tf32r(v.z); v.w = tf32r(v.w);
            *(float4*)&Bs[bkr * BST + bnc] = v;
            v = b1v; v.x = tf32r(v.x); v.y = tf32r(v.y); v.z = tf32r(v.z); v.w = tf32r(v.w);
            *(float4*)&Bs[bkr * BST + bnc + 4] = v;
        }
        __syncthreads();
        if (c < 63) {
            const float* xn = xg + (c + 1) * 16;
            a0v = *(const float4*)xn;
            a1v = *(const float4*)(xn + 4);
            const float* wn_ = wgp + (size_t)(c + 1) * 16 * NH;
            b0v = *(const float4*)wn_;
            b1v = *(const float4*)(wn_ + 4);
        }
        #pragma unroll
        for (int ka = 0; ka < 2; ka++) {
            uint32_t af[2][4];
            #pragma unroll
            for (int ma = 0; ma < 2; ma++) {
                const int mr = wm * 32 + ma * 16;
                af[ma][0] = __float_as_uint(As[(mr + g) * AST + ka * 8 + tt]);
                af[ma][1] = __float_as_uint(As[(mr + g + 8) * AST + ka * 8 + tt]);
                af[ma][2] = __float_as_uint(As[(mr + g) * AST + ka * 8 + tt + 4]);
                af[ma][3] = __float_as_uint(As[(mr + g + 8) * AST + ka * 8 + tt + 4]);
            }
            #pragma unroll
            for (int na = 0; na < 8; na++) {
                uint32_t bf[2];
                bf[0] = __float_as_uint(Bs[(ka * 8 + tt) * BST + wn * 64 + na * 8 + g]);
                bf[1] = __float_as_uint(Bs[(ka * 8 + tt + 4) * BST + wn * 64 + na * 8 + g]);
                MMA_TF32(acc[0][na], af[0], bf);
                MMA_TF32(acc[1][na], af[1], bf);
            }
        }
    }

    // epilogue: bias + relu, direct stores (c0/c1 contiguous -> float2)
    // FIX (R8): bias indexed by GLOBAL column n0+colb (was tile-local colb).
    float* hb = g_hid + (size_t)grp * NB * 256;
    #pragma unroll
    for (int ma = 0; ma < 2; ma++) {
        const int r_ = row0 + wm * 32 + ma * 16 + g;
        #pragma unroll
        for (int na = 0; na < 8; na++) {
            const int colb = wn * 64 + na * 8 + 2 * tt;
            const float bb0 = bias_s[n0 + colb];
            const float bb1 = bias_s[n0 + colb + 1];
            float2 v0, v1;
            v0.x = fmaxf(acc[ma][na][0] + bb0, 0.f);
            v0.y = fmaxf(acc[ma][na][1] + bb1, 0.f);
            v1.x = fmaxf(acc[ma][na][2] + bb0, 0.f);
            v1.y = fmaxf(acc[ma][na][3] + bb1, 0.f);
            *(float2*)&hb[(size_t)r_ * 256 + n0 + colb] = v0;
            *(float2*)&hb[(size_t)(r_ + 8) * 256 + n0 + colb] = v1;
        }
    }
}

// ---------------------------------------------------------------------------
// Kernel 2: gates, Wg staged in smem (odd stride -> conflict-free), 8 rows/warp
// ---------------------------------------------------------------------------
template <int G>
__global__ __launch_bounds__(256) void gate_kernel(const float* __restrict__ x,
                                                   const float* __restrict__ Wg,
                                                   const float* __restrict__ bg,
                                                   int off) {
    constexpr int P = G + 1;  // odd stride
    float* wsh = (float*)dynsm;          // [1024][P]
    float* bgs = wsh + 1024 * P;         // [G]
    float* sred = bgs + G;               // [8][G]
    const int t = threadIdx.x, w = t >> 5, lane = t & 31;

    for (int i = t; i < 1024 * G; i += 256) {
        const int f = i / G;
        wsh[f * P + (i - f * G)] = Wg[i];
    }
    if (t < G) bgs[t] = bg[t];
    __syncthreads();

    const size_t brow0 = (size_t)blockIdx.x * 64 + w * 8;
    for (int r = 0; r < 8; r++) {
        const float* xr = x + (brow0 + r) * NF;
        float acc[G];
        #pragma unroll
        for (int c = 0; c < G; c++) acc[c] = 0.f;
        for (int i = 0; i < 32; i++) {
            const float xv = xr[lane + 32 * i];
            const float* wr = wsh + (lane + 32 * i) * P;
            #pragma unroll
            for (int c = 0; c < G; c++) acc[c] += xv * wr[c];
        }
        #pragma unroll
        for (int c = 0; c < G; c++) {
            #pragma unroll
            for (int o = 16; o > 0; o >>= 1)
                acc[c] += __shfl_xor_sync(0xffffffffu, acc[c], o);
        }
        if (lane == 0) {
            #pragma unroll
            for (int c = 0; c < G; c++) sred[w * G + c] = acc[c];
        }
        __syncwarp();
        float logit = (lane < G) ? sred[w * G + lane] + bgs[lane] : -1e30f;
        float m = logit;
        #pragma unroll
        for (int o = 16; o > 0; o >>= 1)
            m = fmaxf(m, __shfl_xor_sync(0xffffffffu, m, o));
        float ex = (lane < G) ? expf(logit - m) : 0.f;
        float sum = ex;
        #pragma unroll
        for (int o = 16; o > 0; o >>= 1)
            sum += __shfl_xor_sync(0xffffffffu, sum, o);
        if (lane < G) g_gates[(brow0 + r) * 28 + off + lane] = ex / sum;
    }
}

// ---------------------------------------------------------------------------
// Kernel 3: layer-2 + relu + gated combine (unchanged, verified in R2)
// ---------------------------------------------------------------------------
struct CArgs { const float* W2[3]; const float* b2[3]; };

#define CS_W2  0
#define CS_HS  16384
#define CS_B2  (16384 + 1024)
#define CS_GS  (16384 + 1024 + 256)
#define CS_FLOATS (16384 + 1024 + 256 + 16 * 28)
#define CS_BYTES (CS_FLOATS * 4)

__global__ __launch_bounds__(256) void combine_kernel(CArgs args, float* __restrict__ out) {
    float* cs0 = (float*)dynsm;
    float* W2s = cs0 + CS_W2;
    float* Hs  = cs0 + CS_HS;
    float* b2s = cs0 + CS_B2;
    float* gsh = cs0 + CS_GS;

    const int t = threadIdx.x;
    const int row0 = blockIdx.x * 16;

    for (int i = t; i < 16 * 28; i += 256)
        gsh[i] = g_gates[(size_t)(row0 + i / 28) * 28 + (i % 28)];

    float oA[16], oS[16], oB[16];
    #pragma unroll
    for (int r = 0; r < 16; r++) { oA[r] = 0.f; oS[r] = 0.f; oB[r] = 0.f; }

    const int hr = t >> 4;
    const int h4 = (t & 15) * 4;

    for (int e = 0; e < 12; e++) {
        const int grp = e >> 2;
        const int el  = e & 3;
        __syncthreads();
        const float4* w2g = (const float4*)(args.W2[grp] + (size_t)el * NH * ND);
        float4* w2s4 = (float4*)W2s;
        #pragma unroll
        for (int i = 0; i < 16; i++) w2s4[i * 256 + t] = w2g[i * 256 + t];
        b2s[t] = args.b2[grp][el * 256 + t];
        *(float4*)&Hs[hr * 64 + h4] =
            *(const float4*)(g_hid + (size_t)grp * NB * 256 +
                             (size_t)(row0 + hr) * 256 + el * 64 + h4);
        __syncthreads();

        unsigned long long tp[16];
        #pragma unroll
        for (int r = 0; r < 16; r++) tp[r] = 0ull;

        #pragma unroll
        for (int hp = 0; hp < 32; hp++) {
            const float w0 = W2s[(2 * hp) * 256 + t];
            const float w1 = W2s[(2 * hp + 1) * 256 + t];
            unsigned long long wpk;
            PACK2(wpk, __float_as_uint(w0), __float_as_uint(w1));
            #pragma unroll
            for (int r = 0; r < 16; r++) {
                const unsigned long long hv = *(const unsigned long long*)&Hs[r * 64 + 2 * hp];
                FMA2(tp[r], hv, wpk);
            }
        }

        #pragma unroll
        for (int r = 0; r < 16; r++) {
            unsigned int u0, u1;
            UNPACK2(u0, u1, tp[r]);
            float val = __uint_as_float(u0) + __uint_as_float(u1) + b2s[t];
            val = fmaxf(val, 0.f);
            const float* g = &gsh[r * 28];
            const float cS = g[8 + e];
            float cA = 0.f, cB = 0.f;
            if (e < 8) cA = g[e];
            if (e >= 8) cB = g[12 + e];
            else if (e >= 4) cB = g[20 + e];
            oA[r] += cA * val;
            oS[r] += cS * val;
            oB[r] += cB * val;
        }
    }

    #pragma unroll
    for (int r = 0; r < 16; r++) {
        const size_t rowoff = (size_t)(row0 + r) * 256 + t;
        out[rowoff]              = oA[r];
        out[(size_t)BD + rowoff] = oS[r];
        out[2ull * BD + rowoff]  = oB[r];
    }
}

// ---------------------------------------------------------------------------
// Launcher
// ---------------------------------------------------------------------------
extern "C" void kernel_launch(void* const* d_in, const int* in_sizes, int n_in,
                              void* d_out, int out_size) {
    (void)in_sizes; (void)n_in; (void)out_size;
    const float* x_A = (const float*)d_in[0];
    const float* x_S = (const float*)d_in[1];
    const float* x_B = (const float*)d_in[2];
    const float* W1A = (const float*)d_in[3];
    const float* b1A = (const float*)d_in[4];
    const float* W2A = (const float*)d_in[5];
    const float* b2A = (const float*)d_in[6];
    const float* W1S = (const float*)d_in[7];
    const float* b1S = (const float*)d_in[8];
    const float* W2S = (const float*)d_in[9];
    const float* b2S = (const float*)d_in[10];
    const float* W1B = (const float*)d_in[11];
    const float* b1B = (const float*)d_in[12];
    const float* W2B = (const float*)d_in[13];
    const float* b2B = (const float*)d_in[14];
    const float* WgA = (const float*)d_in[15];
    const float* bgA = (const float*)d_in[16];
    const float* WgB = (const float*)d_in[17];
    const float* bgB = (const float*)d_in[18];
    const float* WgS = (const float*)d_in[19];
    const float* bgS = (const float*)d_in[20];
    float* out = (float*)d_out;

    cudaFuncSetAttribute(gate_kernel<8>, cudaFuncAttributeMaxDynamicSharedMemorySize,
                         (1024 * 9 + 8 + 64) * 4);
    cudaFuncSetAttribute(gate_kernel<12>, cudaFuncAttributeMaxDynamicSharedMemorySize,
                         (1024 * 13 + 12 + 96) * 4);
    cudaFuncSetAttribute(combine_kernel, cudaFuncAttributeMaxDynamicSharedMemorySize, CS_BYTES);

    G1Args g1;
    g1.x[0] = x_A;  g1.x[1] = x_S;  g1.x[2] = x_B;
    g1.W1[0] = W1A; g1.W1[1] = W1S; g1.W1[2] = W1B;
    g1.b1[0] = b1A; g1.b1[1] = b1S; g1.b1[2] = b1B;
    gemm1_kernel<<<dim3(NB / 128, 2, 3), 256>>>(g1);

    gate_kernel<8><<<NB / 64, 256, (1024 * 9 + 8 + 64) * 4>>>(x_A, WgA, bgA, 0);
    gate_kernel<12><<<NB / 64, 256, (1024 * 13 + 12 + 96) * 4>>>(x_S, WgS, bgS, 8);
    gate_kernel<8><<<NB / 64, 256, (1024 * 9 + 8 + 64) * 4>>>(x_B, WgB, bgB, 20);

    CArgs c2;
    c2.W2[0] = W2A; c2.W2[1] = W2S; c2.W2[2] = W2B;
    c2.b2[0] = b2A; c2.b2[1] = b2S; c2.b2[2] = b2B;
    combine_kernel<<<NB / 16, 256, CS_BYTES>>>(c2, out);
}

// round 10
// speedup vs baseline: 1.7331x; 1.6633x over previous
#include <cuda_runtime.h>
#include <cuda_bf16.h>
#include <cstdint>

// Problem dims
#define NB   16384
#define NF   1024
#define NH   64
#define ND   256
#define BD   (NB * ND)

// ---------------------------------------------------------------------------
// Scratch (device globals — no allocations allowed)
// ---------------------------------------------------------------------------
__device__ float g_hid[3ull * NB * 256];    // per-group hidden [B, 256], relu'd
__device__ float g_gates[(size_t)NB * 28];  // per row: gA[8] | gS[12] | gB[8]

extern __shared__ char dynsm[];

// ---------------------------------------------------------------------------
// Helpers
// ---------------------------------------------------------------------------
__device__ __forceinline__ float tf32r(float x) {      // round-to-nearest tf32
    uint32_t u;
    asm("cvt.rna.tf32.f32 %0, %1;" : "=r"(u) : "f"(x));
    return __uint_as_float(u);
}

// m16n8k8 tf32 MMA (plain sm_80+ PTX — works on non-'a' sm_103 target)
#define MMA_TF32(c, a, b) \
    asm("mma.sync.aligned.m16n8k8.row.col.f32.tf32.tf32.f32 " \
        "{%0,%1,%2,%3}, {%4,%5,%6,%7}, {%8,%9}, {%0,%1,%2,%3};" \
        : "+f"((c)[0]), "+f"((c)[1]), "+f"((c)[2]), "+f"((c)[3]) \
        : "r"((a)[0]), "r"((a)[1]), "r"((a)[2]), "r"((a)[3]), \
          "r"((b)[0]), "r"((b)[1]))

// Packed f32x2 helpers (combine kernel)
#define FMA2(acc, a, b) asm("fma.rn.f32x2 %0, %1, %2, %0;" : "+l"(acc) : "l"(a), "l"(b))
#define PACK2(dst, lo, hi) asm("mov.b64 %0, {%1, %2};" : "=l"(dst) : "r"(lo), "r"(hi))
#define UNPACK2(lo, hi, v) asm("mov.b64 {%0, %1}, %2;" : "=r"(lo), "=r"(hi) : "l"(v))

// ---------------------------------------------------------------------------
// Kernel 1: layer-1 via mma.sync tf32. CTA tile 128x128, K-chunk 16.
// 2-stage smem double buffer, ONE __syncthreads per chunk.
// 8 warps as 4(m) x 2(n); warp tile 32x64 = 2 m-atoms x 8 n-atoms.
//   C[b, e*64+h] = relu( sum_f x[b,f] * W1[e,f,h] + b1[e,h] )
// ---------------------------------------------------------------------------
struct G1Args { const float* x[3]; const float* W1[3]; const float* b1[3]; };

#define AST 20    // A smem row stride (floats)
#define BST 136   // B smem row stride (floats)

__global__ __launch_bounds__(256) void gemm1_kernel(G1Args args) {
    __shared__ float As[2][128 * AST];   // [m][k], k-chunk 16
    __shared__ float Bs[2][16 * BST];    // [k][n], n tile 128
    __shared__ float bias_s[256];

    const int t = threadIdx.x, lane = t & 31, w = t >> 5;
    const int wm = w >> 1, wn = w & 1;       // warp grid 4x2
    const int g = lane >> 2, tt = lane & 3;  // fragment coords
    const int row0 = blockIdx.x * 128;
    const int n0   = blockIdx.y * 128;
    const int grp  = blockIdx.z;
    const float* __restrict__ x  = args.x[grp];
    const float* __restrict__ W1 = args.W1[grp];

    bias_s[t] = args.b1[grp][t];

    // staging assignments
    const int arow = t >> 1;             // A row 0..127, 2 threads/row
    const int acb  = (t & 1) * 8;        // A k-offset 0 or 8
    const int bkr  = t >> 4;             // B k-row 0..15
    const int bnc  = (t & 15) * 8;       // B n-offset 0..120
    const int be   = (n0 + bnc) >> 6;    // expert of this col run
    const int bh   = (n0 + bnc) & 63;

    const float* xg  = x + (size_t)(row0 + arow) * NF + acb;
    const float* wgp = W1 + (size_t)be * NF * NH + (size_t)bkr * NH + bh;

    float acc[2][8][4];
    #pragma unroll
    for (int ma = 0; ma < 2; ma++)
        #pragma unroll
        for (int na = 0; na < 8; na++)
            #pragma unroll
            for (int i = 0; i < 4; i++) acc[ma][na][i] = 0.f;

    float4 a0v, a1v, b0v, b1v;   // register-held chunk

    auto ldg = [&](int c) {
        const float* xn = xg + c * 16;
        a0v = *(const float4*)xn;
        a1v = *(const float4*)(xn + 4);
        const float* wn_ = wgp + (size_t)c * 16 * NH;
        b0v = *(const float4*)wn_;
        b1v = *(const float4*)(wn_ + 4);
    };
    auto sts = [&](int s) {
        float4 v;
        v = a0v; v.x = tf32r(v.x); v.y = tf32r(v.y); v.z = tf32r(v.z); v.w = tf32r(v.w);
        *(float4*)&As[s][arow * AST + acb] = v;
        v = a1v; v.x = tf32r(v.x); v.y = tf32r(v.y); v.z = tf32r(v.z); v.w = tf32r(v.w);
        *(float4*)&As[s][arow * AST + acb + 4] = v;
        v = b0v; v.x = tf32r(v.x); v.y = tf32r(v.y); v.z = tf32r(v.z); v.w = tf32r(v.w);
        *(float4*)&Bs[s][bkr * BST + bnc] = v;
        v = b1v; v.x = tf32r(v.x); v.y = tf32r(v.y); v.z = tf32r(v.z); v.w = tf32r(v.w);
        *(float4*)&Bs[s][bkr * BST + bnc + 4] = v;
    };

    ldg(0);
    sts(0);
    ldg(1);                 // regs now hold chunk 1
    __syncthreads();

    for (int c = 0; c < 64; c++) {
        const int s = c & 1;
        if (c + 1 < 64) sts((c + 1) & 1);   // buffer freed by compute(c-1) at prev sync
        if (c + 2 < 64) ldg(c + 2);         // consumed next iteration -> latency hidden

        #pragma unroll
        for (int ka = 0; ka < 2; ka++) {
            uint32_t af[2][4];
            #pragma unroll
            for (int ma = 0; ma < 2; ma++) {
                const int mr = wm * 32 + ma * 16;
                af[ma][0] = __float_as_uint(As[s][(mr + g) * AST + ka * 8 + tt]);
                af[ma][1] = __float_as_uint(As[s][(mr + g + 8) * AST + ka * 8 + tt]);
                af[ma][2] = __float_as_uint(As[s][(mr + g) * AST + ka * 8 + tt + 4]);
                af[ma][3] = __float_as_uint(As[s][(mr + g + 8) * AST + ka * 8 + tt + 4]);
            }
            #pragma unroll
            for (int na = 0; na < 8; na++) {
                uint32_t bf[2];
                bf[0] = __float_as_uint(Bs[s][(ka * 8 + tt) * BST + wn * 64 + na * 8 + g]);
                bf[1] = __float_as_uint(Bs[s][(ka * 8 + tt + 4) * BST + wn * 64 + na * 8 + g]);
                MMA_TF32(acc[0][na], af[0], bf);
                MMA_TF32(acc[1][na], af[1], bf);
            }
        }
        __syncthreads();
    }

    // epilogue: bias + relu, direct stores (bias indexed by GLOBAL column)
    float* hb = g_hid + (size_t)grp * NB * 256;
    #pragma unroll
    for (int ma = 0; ma < 2; ma++) {
        const int r_ = row0 + wm * 32 + ma * 16 + g;
        #pragma unroll
        for (int na = 0; na < 8; na++) {
            const int colb = wn * 64 + na * 8 + 2 * tt;
            const float bb0 = bias_s[n0 + colb];
            const float bb1 = bias_s[n0 + colb + 1];
            float2 v0, v1;
            v0.x = fmaxf(acc[ma][na][0] + bb0, 0.f);
            v0.y = fmaxf(acc[ma][na][1] + bb1, 0.f);
            v1.x = fmaxf(acc[ma][na][2] + bb0, 0.f);
            v1.y = fmaxf(acc[ma][na][3] + bb1, 0.f);
            *(float2*)&hb[(size_t)r_ * 256 + n0 + colb] = v0;
            *(float2*)&hb[(size_t)(r_ + 8) * 256 + n0 + colb] = v1;
        }
    }
}

// ---------------------------------------------------------------------------
// Kernel 2: gates. Smem-staged Wg (odd stride -> conflict-free LDS).
// grid = NB/16 blocks (16 rows/block, 2 rows/warp) for occupancy.
// ---------------------------------------------------------------------------
template <int G>
__global__ __launch_bounds__(256) void gate_kernel(const float* __restrict__ x,
                                                   const float* __restrict__ Wg,
                                                   const float* __restrict__ bg,
                                                   int off) {
    constexpr int P = G + 1;  // odd stride
    float* wsh = (float*)dynsm;          // [1024][P]
    float* bgs = wsh + 1024 * P;         // [G]
    float* sred = bgs + G;               // [8][G]
    const int t = threadIdx.x, w = t >> 5, lane = t & 31;

    for (int i = t; i < 1024 * G; i += 256) {
        const int f = i / G;
        wsh[f * P + (i - f * G)] = Wg[i];
    }
    if (t < G) bgs[t] = bg[t];
    __syncthreads();

    const size_t brow0 = (size_t)blockIdx.x * 16 + w * 2;
    #pragma unroll
    for (int r = 0; r < 2; r++) {
        const float* xr = x + (brow0 + r) * NF;
        float acc[G];
        #pragma unroll
        for (int c = 0; c < G; c++) acc[c] = 0.f;
        for (int i = 0; i < 32; i++) {
            const float xv = xr[lane + 32 * i];
            const float* wr = wsh + (lane + 32 * i) * P;
            #pragma unroll
            for (int c = 0; c < G; c++) acc[c] += xv * wr[c];
        }
        #pragma unroll
        for (int c = 0; c < G; c++) {
            #pragma unroll
            for (int o = 16; o > 0; o >>= 1)
                acc[c] += __shfl_xor_sync(0xffffffffu, acc[c], o);
        }
        if (lane == 0) {
            #pragma unroll
            for (int c = 0; c < G; c++) sred[w * G + c] = acc[c];
        }
        __syncwarp();
        float logit = (lane < G) ? sred[w * G + lane] + bgs[lane] : -1e30f;
        float m = logit;
        #pragma unroll
        for (int o = 16; o > 0; o >>= 1)
            m = fmaxf(m, __shfl_xor_sync(0xffffffffu, m, o));
        float ex = (lane < G) ? expf(logit - m) : 0.f;
        float sum = ex;
        #pragma unroll
        for (int o = 16; o > 0; o >>= 1)
            sum += __shfl_xor_sync(0xffffffffu, sum, o);
        if (lane < G) g_gates[(brow0 + r) * 28 + off + lane] = ex / sum;
    }
}

// ---------------------------------------------------------------------------
// Kernel 3: layer-2 + relu + gated combine (unchanged, verified)
// ---------------------------------------------------------------------------
struct CArgs { const float* W2[3]; const float* b2[3]; };

#define CS_W2  0
#define CS_HS  16384
#define CS_B2  (16384 + 1024)
#define CS_GS  (16384 + 1024 + 256)
#define CS_FLOATS (16384 + 1024 + 256 + 16 * 28)
#define CS_BYTES (CS_FLOATS * 4)

__global__ __launch_bounds__(256) void combine_kernel(CArgs args, float* __restrict__ out) {
    float* cs0 = (float*)dynsm;
    float* W2s = cs0 + CS_W2;
    float* Hs  = cs0 + CS_HS;
    float* b2s = cs0 + CS_B2;
    float* gsh = cs0 + CS_GS;

    const int t = threadIdx.x;
    const int row0 = blockIdx.x * 16;

    for (int i = t; i < 16 * 28; i += 256)
        gsh[i] = g_gates[(size_t)(row0 + i / 28) * 28 + (i % 28)];

    float oA[16], oS[16], oB[16];
    #pragma unroll
    for (int r = 0; r < 16; r++) { oA[r] = 0.f; oS[r] = 0.f; oB[r] = 0.f; }

    const int hr = t >> 4;
    const int h4 = (t & 15) * 4;

    for (int e = 0; e < 12; e++) {
        const int grp = e >> 2;
        const int el  = e & 3;
        __syncthreads();
        const float4* w2g = (const float4*)(args.W2[grp] + (size_t)el * NH * ND);
        float4* w2s4 = (float4*)W2s;
        #pragma unroll
        for (int i = 0; i < 16; i++) w2s4[i * 256 + t] = w2g[i * 256 + t];
        b2s[t] = args.b2[grp][el * 256 + t];
        *(float4*)&Hs[hr * 64 + h4] =
            *(const float4*)(g_hid + (size_t)grp * NB * 256 +
                             (size_t)(row0 + hr) * 256 + el * 64 + h4);
        __syncthreads();

        unsigned long long tp[16];
        #pragma unroll
        for (int r = 0; r < 16; r++) tp[r] = 0ull;

        #pragma unroll
        for (int hp = 0; hp < 32; hp++) {
            const float w0 = W2s[(2 * hp) * 256 + t];
            const float w1 = W2s[(2 * hp + 1) * 256 + t];
            unsigned long long wpk;
            PACK2(wpk, __float_as_uint(w0), __float_as_uint(w1));
            #pragma unroll
            for (int r = 0; r < 16; r++) {
                const unsigned long long hv = *(const unsigned long long*)&Hs[r * 64 + 2 * hp];
                FMA2(tp[r], hv, wpk);
            }
        }

        #pragma unroll
        for (int r = 0; r < 16; r++) {
            unsigned int u0, u1;
            UNPACK2(u0, u1, tp[r]);
            float val = __uint_as_float(u0) + __uint_as_float(u1) + b2s[t];
            val = fmaxf(val, 0.f);
            const float* g = &gsh[r * 28];
            const float cS = g[8 + e];
            float cA = 0.f, cB = 0.f;
            if (e < 8) cA = g[e];
            if (e >= 8) cB = g[12 + e];
            else if (e >= 4) cB = g[20 + e];
            oA[r] += cA * val;
            oS[r] += cS * val;
            oB[r] += cB * val;
        }
    }

    #pragma unroll
    for (int r = 0; r < 16; r++) {
        const size_t rowoff = (size_t)(row0 + r) * 256 + t;
        out[rowoff]              = oA[r];
        out[(size_t)BD + rowoff] = oS[r];
        out[2ull * BD + rowoff]  = oB[r];
    }
}

// ---------------------------------------------------------------------------
// Launcher
// ---------------------------------------------------------------------------
extern "C" void kernel_launch(void* const* d_in, const int* in_sizes, int n_in,
                              void* d_out, int out_size) {
    (void)in_sizes; (void)n_in; (void)out_size;
    const float* x_A = (const float*)d_in[0];
    const float* x_S = (const float*)d_in[1];
    const float* x_B = (const float*)d_in[2];
    const float* W1A = (const float*)d_in[3];
    const float* b1A = (const float*)d_in[4];
    const float* W2A = (const float*)d_in[5];
    const float* b2A = (const float*)d_in[6];
    const float* W1S = (const float*)d_in[7];
    const float* b1S = (const float*)d_in[8];
    const float* W2S = (const float*)d_in[9];
    const float* b2S = (const float*)d_in[10];
    const float* W1B = (const float*)d_in[11];
    const float* b1B = (const float*)d_in[12];
    const float* W2B = (const float*)d_in[13];
    const float* b2B = (const float*)d_in[14];
    const float* WgA = (const float*)d_in[15];
    const float* bgA = (const float*)d_in[16];
    const float* WgB = (const float*)d_in[17];
    const float* bgB = (const float*)d_in[18];
    const float* WgS = (const float*)d_in[19];
    const float* bgS = (const float*)d_in[20];
    float* out = (float*)d_out;

    cudaFuncSetAttribute(gate_kernel<8>, cudaFuncAttributeMaxDynamicSharedMemorySize,
                         (1024 * 9 + 8 + 64) * 4);
    cudaFuncSetAttribute(gate_kernel<12>, cudaFuncAttributeMaxDynamicSharedMemorySize,
                         (1024 * 13 + 12 + 96) * 4);
    cudaFuncSetAttribute(combine_kernel, cudaFuncAttributeMaxDynamicSharedMemorySize, CS_BYTES);

    G1Args g1;
    g1.x[0] = x_A;  g1.x[1] = x_S;  g1.x[2] = x_B;
    g1.W1[0] = W1A; g1.W1[1] = W1S; g1.W1[2] = W1B;
    g1.b1[0] = b1A; g1.b1[1] = b1S; g1.b1[2] = b1B;
    gemm1_kernel<<<dim3(NB / 128, 2, 3), 256>>>(g1);

    gate_kernel<8><<<NB / 16, 256, (1024 * 9 + 8 + 64) * 4>>>(x_A, WgA, bgA, 0);
    gate_kernel<12><<<NB / 16, 256, (1024 * 13 + 12 + 96) * 4>>>(x_S, WgS, bgS, 8);
    gate_kernel<8><<<NB / 16, 256, (1024 * 9 + 8 + 64) * 4>>>(x_B, WgB, bgB, 20);

    CArgs c2;
    c2.W2[0] = W2A; c2.W2[1] = W2S; c2.W2[2] = W2B;
    c2.b2[0] = b2A; c2.b2[1] = b2S; c2.b2[2] = b2B;
    combine_kernel<<<NB / 16, 256, CS_BYTES>>>(c2, out);
}